// round 1
// baseline (speedup 1.0000x reference)
#include <cuda_runtime.h>
#include <math.h>

// Problem constants: B=1024, H=32, N=25, F=D=128
#define BH      32768          // B*H rows
#define NNEIGH  25
#define NK      26             // self + neighbours
#define FDIM    128
#define DDIM    128
#define XN_ROW  (NNEIGH * FDIM)   // 3200 floats per (b,h) in x_neigh

// Scratch (device globals: allocation-free per harness rules)
__device__ float g_wa[2 * FDIM];             // [0:128) = W@a_self, [128:256) = W@a_neigh
__device__ float g_xagg[(size_t)BH * FDIM];  // aggregated input rows, 16 MB

// ---------------------------------------------------------------------------
// Kernel 0: wa = W @ a  (two 128-length GEMVs). One block, 128 threads.
// ---------------------------------------------------------------------------
__global__ void wa_kernel(const float* __restrict__ W,
                          const float* __restrict__ a_s,
                          const float* __restrict__ a_n) {
    int f = threadIdx.x;   // 0..127
    float s = 0.f, n = 0.f;
    const float* wr = W + (size_t)f * DDIM;
#pragma unroll 8
    for (int d = 0; d < DDIM; d++) {
        float w = wr[d];
        s = fmaf(w, a_s[d], s);
        n = fmaf(w, a_n[d], n);
    }
    g_wa[f]        = s;
    g_wa[FDIM + f] = n;
}

// ---------------------------------------------------------------------------
// Kernel 1: per (b,h) attention aggregation in input space.
// One block per row (32768 blocks), 128 threads (4 warps).
// ---------------------------------------------------------------------------
__global__ void __launch_bounds__(128)
agg_kernel(const float* __restrict__ x_self,
           const float* __restrict__ x_neigh) {
    __shared__ float xs[NK * FDIM];      // 26 x 128 staged rows (13.3 KB)
    __shared__ float wa_s[FDIM];
    __shared__ float wa_n[FDIM];
    __shared__ float sc[32];             // [0..25]=scores->probs, [26]=self score

    const int t   = threadIdx.x;
    const int row = blockIdx.x;

    wa_s[t] = g_wa[t];
    wa_n[t] = g_wa[FDIM + t];

    // stage x_self row
    xs[t] = x_self[(size_t)row * FDIM + t];

    // stage x_neigh rows: 3200 contiguous floats = 800 float4 (16B-aligned base)
    const float4* xn  = reinterpret_cast<const float4*>(x_neigh + (size_t)row * XN_ROW);
    float4*       xs4 = reinterpret_cast<float4*>(xs + FDIM);
    for (int i = t; i < XN_ROW / 4; i += 128) xs4[i] = xn[i];
    __syncthreads();

    const int warp = t >> 5, lane = t & 31;

    // 27 dot products of length 128 (k=26 is the "self" score with wa_self)
    for (int k = warp; k < 27; k += 4) {
        const float* xr = (k == 26) ? xs : (xs + k * FDIM);
        const float* wa = (k == 26) ? wa_s : wa_n;
        float v = 0.f;
        v = fmaf(xr[lane],      wa[lane],      v);
        v = fmaf(xr[lane + 32], wa[lane + 32], v);
        v = fmaf(xr[lane + 64], wa[lane + 64], v);
        v = fmaf(xr[lane + 96], wa[lane + 96], v);
#pragma unroll
        for (int o = 16; o; o >>= 1) v += __shfl_xor_sync(0xffffffffu, v, o);
        if (lane == 0) sc[k] = v;
    }
    __syncthreads();

    // softmax over 26 entries (warp 0)
    if (warp == 0) {
        float ss = sc[26];
        float u  = -INFINITY;
        if (lane < NK) {
            u = ss + sc[lane];
            u = (u > 0.f) ? u : 0.2f * u;   // LeakyReLU(0.2)
        }
        float m = u;
#pragma unroll
        for (int o = 16; o; o >>= 1) m = fmaxf(m, __shfl_xor_sync(0xffffffffu, m, o));
        float e = (lane < NK) ? expf(u - m) : 0.f;
        float s = e;
#pragma unroll
        for (int o = 16; o; o >>= 1) s += __shfl_xor_sync(0xffffffffu, s, o);
        if (lane < NK) sc[lane] = e / s;
    }
    __syncthreads();

    // x_agg[f] = sum_k p_k * x_all[k][f]
    float acc = 0.f;
#pragma unroll
    for (int k = 0; k < NK; k++) acc = fmaf(sc[k], xs[k * FDIM + t], acc);
    g_xagg[(size_t)row * FDIM + t] = acc;
}

// ---------------------------------------------------------------------------
// Kernel 2: out = relu(g_xagg[32768,128] @ W[128,128])
// Classic smem-tiled SGEMM: BM=BN=128, BK=16, 256 threads, 8x8 micro-tile.
// ---------------------------------------------------------------------------
#define K2_BM 128
#define K2_BN 128
#define K2_BK 16

__global__ void __launch_bounds__(256)
gemm_relu_kernel(const float* __restrict__ W, float* __restrict__ out) {
    __shared__ float As[K2_BK][K2_BM];
    __shared__ float Bs[K2_BK][K2_BN];

    const int tid = threadIdx.x;
    const int ty  = tid >> 4;       // 0..15 -> row group
    const int tx  = tid & 15;       // 0..15 -> col group
    const size_t rowbase = (size_t)blockIdx.x * K2_BM;

    float acc[8][8];
#pragma unroll
    for (int i = 0; i < 8; i++)
#pragma unroll
        for (int j = 0; j < 8; j++) acc[i][j] = 0.f;

    for (int k0 = 0; k0 < FDIM; k0 += K2_BK) {
        // load A tile 128x16 (transposed into As[k][r])
#pragma unroll
        for (int i = tid; i < K2_BM * K2_BK; i += 256) {
            int r = i >> 4, k = i & 15;
            As[k][r] = g_xagg[(rowbase + r) * FDIM + k0 + k];
        }
        // load B tile 16x128
#pragma unroll
        for (int i = tid; i < K2_BK * K2_BN; i += 256) {
            int k = i >> 7, d = i & 127;
            Bs[k][d] = W[(size_t)(k0 + k) * DDIM + d];
        }
        __syncthreads();

#pragma unroll
        for (int kk = 0; kk < K2_BK; kk++) {
            float a[8], b[8];
            // vectorized smem reads (8 floats = 2 x float4, 16B aligned)
            *reinterpret_cast<float4*>(&a[0]) = *reinterpret_cast<const float4*>(&As[kk][ty * 8]);
            *reinterpret_cast<float4*>(&a[4]) = *reinterpret_cast<const float4*>(&As[kk][ty * 8 + 4]);
            *reinterpret_cast<float4*>(&b[0]) = *reinterpret_cast<const float4*>(&Bs[kk][tx * 8]);
            *reinterpret_cast<float4*>(&b[4]) = *reinterpret_cast<const float4*>(&Bs[kk][tx * 8 + 4]);
#pragma unroll
            for (int i = 0; i < 8; i++)
#pragma unroll
                for (int j = 0; j < 8; j++) acc[i][j] = fmaf(a[i], b[j], acc[i][j]);
        }
        __syncthreads();
    }

#pragma unroll
    for (int i = 0; i < 8; i++) {
        size_t r = rowbase + ty * 8 + i;
#pragma unroll
        for (int j = 0; j < 8; j++) {
            float v = acc[i][j];
            out[r * DDIM + tx * 8 + j] = (v > 0.f) ? v : 0.f;
        }
    }
}

// ---------------------------------------------------------------------------
extern "C" void kernel_launch(void* const* d_in, const int* in_sizes, int n_in,
                              void* d_out, int out_size) {
    const float* x_self  = (const float*)d_in[0];   // [1024,32,128]
    const float* x_neigh = (const float*)d_in[1];   // [1024,32,25,128]
    const float* w_feat  = (const float*)d_in[2];   // [128,128]
    const float* a_self  = (const float*)d_in[3];   // [128,1]
    const float* a_neigh = (const float*)d_in[4];   // [128,1]
    float*       out     = (float*)d_out;           // [1024,32,128]

    wa_kernel<<<1, 128>>>(w_feat, a_self, a_neigh);
    agg_kernel<<<BH, 128>>>(x_self, x_neigh);
    gemm_relu_kernel<<<BH / K2_BM, 256>>>(w_feat, out);
}